// round 1
// baseline (speedup 1.0000x reference)
#include <cuda_runtime.h>
#include <math.h>

#define BB 8
#define TT 512
#define CC 512
#define HH 8
#define DH 64
#define CF 2048
#define MTOK (BB*TT)      // 4096
#define VV 512
#define NSTEPS 4
#define ATT_SCALE 0.125f  // 1/sqrt(64)

// ---------------- scratch (device globals: no allocations allowed) ----------
__device__ float g_x [MTOK*CC];
__device__ float g_xn[MTOK*CC];
__device__ float g_q [MTOK*CC];
__device__ float g_k [MTOK*CC];
__device__ float g_v [MTOK*CC];
__device__ float g_y [MTOK*CC];
__device__ float g_h [MTOK*CF];
__device__ float g_att[(size_t)BB*HH*TT*TT];

// ---------------- block reductions ----------------
__device__ __forceinline__ float block_reduce_sum(float v, float* sm) {
    #pragma unroll
    for (int o = 16; o; o >>= 1) v += __shfl_xor_sync(0xffffffffu, v, o);
    int w = threadIdx.x >> 5;
    if ((threadIdx.x & 31) == 0) sm[w] = v;
    __syncthreads();
    if (threadIdx.x < 32) {
        float x = (threadIdx.x < 8) ? sm[threadIdx.x] : 0.0f;
        #pragma unroll
        for (int o = 4; o; o >>= 1) x += __shfl_xor_sync(0xffffffffu, x, o);
        if (threadIdx.x == 0) sm[0] = x;
    }
    __syncthreads();
    float r = sm[0];
    __syncthreads();
    return r;
}

__device__ __forceinline__ float block_reduce_max(float v, float* sm) {
    #pragma unroll
    for (int o = 16; o; o >>= 1) v = fmaxf(v, __shfl_xor_sync(0xffffffffu, v, o));
    int w = threadIdx.x >> 5;
    if ((threadIdx.x & 31) == 0) sm[w] = v;
    __syncthreads();
    if (threadIdx.x < 32) {
        float x = (threadIdx.x < 8) ? sm[threadIdx.x] : -1e30f;
        #pragma unroll
        for (int o = 4; o; o >>= 1) x = fmaxf(x, __shfl_xor_sync(0xffffffffu, x, o));
        if (threadIdx.x == 0) sm[0] = x;
    }
    __syncthreads();
    float r = sm[0];
    __syncthreads();
    return r;
}

// ---------------- embedding ----------------
__global__ void embed_k(const int* __restrict__ idx, const float* __restrict__ tok,
                        const float* __restrict__ pos) {
    int i = blockIdx.x * blockDim.x + threadIdx.x;   // over MTOK*CC
    int m = i / CC, c = i - m * CC;
    int t = m & (TT - 1);
    g_x[i] = tok[idx[m] * CC + c] + pos[t * CC + c];
}

// ---------------- layernorm: one block per row, 256 thr ----------------
__global__ void ln_k(const float* __restrict__ in, const float* __restrict__ gam,
                     const float* __restrict__ bet, float* __restrict__ out) {
    __shared__ float sm[8];
    int row = blockIdx.x;
    const float* x = in + (size_t)row * CC;
    int t = threadIdx.x;
    float v0 = x[t], v1 = x[t + 256];
    float mean = block_reduce_sum(v0 + v1, sm) * (1.0f / CC);
    float d0 = v0 - mean, d1 = v1 - mean;
    float var = block_reduce_sum(d0 * d0 + d1 * d1, sm) * (1.0f / CC);
    float rstd = rsqrtf(var + 1e-5f);
    float* o = out + (size_t)row * CC;
    o[t]       = d0 * rstd * gam[t]       + bet[t];
    o[t + 256] = d1 * rstd * gam[t + 256] + bet[t + 256];
}

// ---------------- 128x128x8 SGEMM, fused bias / residual / exact GELU ------
// out[M,N] = epi( A[M,K] @ W[K,N] + bias + res ).  M%128==0, N%128==0, K%8==0.
template <bool GELU>
__global__ void __launch_bounds__(256, 2)
gemm128_k(const float* __restrict__ A, const float* __restrict__ Wm,
          const float* __restrict__ bias, const float* __restrict__ res,
          float* __restrict__ out, int M, int N, int K) {
    __shared__ float As[8][128];
    __shared__ float Bs[8][128];
    int tid = threadIdx.x;
    int m0 = blockIdx.y * 128, n0 = blockIdx.x * 128;
    int ty = tid >> 4, tx = tid & 15;

    int aRow = tid >> 1, aCol = (tid & 1) * 4;
    int bRow = tid >> 5, bCol = (tid & 31) * 4;
    const float* Aptr = A  + (size_t)(m0 + aRow) * K + aCol;
    const float* Bptr = Wm + (size_t)bRow * N + n0 + bCol;

    float acc[8][8];
    #pragma unroll
    for (int i = 0; i < 8; i++)
        #pragma unroll
        for (int j = 0; j < 8; j++) acc[i][j] = 0.0f;

    for (int k0 = 0; k0 < K; k0 += 8) {
        float4 av = *(const float4*)(Aptr + k0);
        float4 bv = *(const float4*)(Bptr + (size_t)k0 * N);
        __syncthreads();
        As[aCol + 0][aRow] = av.x;
        As[aCol + 1][aRow] = av.y;
        As[aCol + 2][aRow] = av.z;
        As[aCol + 3][aRow] = av.w;
        *(float4*)&Bs[bRow][bCol] = bv;
        __syncthreads();
        #pragma unroll
        for (int kk = 0; kk < 8; kk++) {
            float4 a0 = *(const float4*)&As[kk][ty * 8];
            float4 a1 = *(const float4*)&As[kk][ty * 8 + 4];
            float4 b0 = *(const float4*)&Bs[kk][tx * 8];
            float4 b1 = *(const float4*)&Bs[kk][tx * 8 + 4];
            float a[8] = {a0.x, a0.y, a0.z, a0.w, a1.x, a1.y, a1.z, a1.w};
            float b[8] = {b0.x, b0.y, b0.z, b0.w, b1.x, b1.y, b1.z, b1.w};
            #pragma unroll
            for (int i = 0; i < 8; i++)
                #pragma unroll
                for (int j = 0; j < 8; j++) acc[i][j] += a[i] * b[j];
        }
    }

    #pragma unroll
    for (int i = 0; i < 8; i++) {
        int m = m0 + ty * 8 + i;
        float*       orow = out + (size_t)m * N + n0 + tx * 8;
        const float* rrow = res ? res + (size_t)m * N + n0 + tx * 8 : nullptr;
        #pragma unroll
        for (int j = 0; j < 8; j++) {
            float val = acc[i][j];
            if (bias) val += bias[n0 + tx * 8 + j];
            if (rrow) val += rrow[j];
            if (GELU) val = 0.5f * val * (1.0f + erff(val * 0.70710678118654752f));
            orow[j] = val;
        }
    }
}

// ---------------- attention: S = (Q Kt) * scale, per (b,h), 64x64 tiles ----
__global__ void attn_scores_k() {
    __shared__ float Qs[64][65];
    __shared__ float Ks[64][65];
    int z = blockIdx.z;                 // b*H + h
    int b = z >> 3, h = z & 7;
    int qt = blockIdx.y * 64, kt = blockIdx.x * 64;
    int tid = threadIdx.x;
    const float* qb = g_q + (size_t)b * TT * CC + h * DH;
    const float* kb = g_k + (size_t)b * TT * CC + h * DH;
    #pragma unroll
    for (int it = 0; it < 4; it++) {
        int r = (tid >> 4) + it * 16;
        int c = (tid & 15) * 4;
        float4 qv = *(const float4*)(qb + (size_t)(qt + r) * CC + c);
        float4 kv = *(const float4*)(kb + (size_t)(kt + r) * CC + c);
        Qs[r][c] = qv.x; Qs[r][c + 1] = qv.y; Qs[r][c + 2] = qv.z; Qs[r][c + 3] = qv.w;
        Ks[r][c] = kv.x; Ks[r][c + 1] = kv.y; Ks[r][c + 2] = kv.z; Ks[r][c + 3] = kv.w;
    }
    __syncthreads();
    int ty = tid >> 4, tx = tid & 15;
    float acc[4][4] = {};
    #pragma unroll 8
    for (int d = 0; d < 64; d++) {
        float a[4], bb[4];
        #pragma unroll
        for (int i = 0; i < 4; i++) a[i]  = Qs[ty * 4 + i][d];
        #pragma unroll
        for (int j = 0; j < 4; j++) bb[j] = Ks[tx * 4 + j][d];
        #pragma unroll
        for (int i = 0; i < 4; i++)
            #pragma unroll
            for (int j = 0; j < 4; j++) acc[i][j] += a[i] * bb[j];
    }
    float* op = g_att + (size_t)z * TT * TT;
    #pragma unroll
    for (int i = 0; i < 4; i++)
        #pragma unroll
        for (int j = 0; j < 4; j++)
            op[(size_t)(qt + ty * 4 + i) * TT + kt + tx * 4 + j] = acc[i][j] * ATT_SCALE;
}

// ---------------- softmax over last dim (512), one block per row -----------
__global__ void softmax_k() {
    __shared__ float sm[8];
    size_t row = blockIdx.x;
    float* p = g_att + row * TT;
    int t = threadIdx.x;
    float v0 = p[t], v1 = p[t + 256];
    float mx = block_reduce_max(fmaxf(v0, v1), sm);
    float e0 = expf(v0 - mx), e1 = expf(v1 - mx);
    float s = block_reduce_sum(e0 + e1, sm);
    float inv = 1.0f / s;
    p[t] = e0 * inv;
    p[t + 256] = e1 * inv;
}

// ---------------- Y = P @ V, per (b,h), M-tile 64, N=64 --------------------
__global__ void attn_pv_k() {
    __shared__ float Ps[64][65];
    __shared__ float Vs[64][65];
    int z = blockIdx.y;
    int b = z >> 3, h = z & 7;
    int qt = blockIdx.x * 64;
    int tid = threadIdx.x;
    int ty = tid >> 4, tx = tid & 15;
    const float* vb = g_v   + (size_t)b * TT * CC + h * DH;
    const float* pb = g_att + (size_t)z * TT * TT;
    float acc[4][4] = {};
    for (int k0 = 0; k0 < TT; k0 += 64) {
        #pragma unroll
        for (int it = 0; it < 4; it++) {
            int r = (tid >> 4) + it * 16;
            int c = (tid & 15) * 4;
            float4 pv = *(const float4*)(pb + (size_t)(qt + r) * TT + k0 + c);
            float4 vv = *(const float4*)(vb + (size_t)(k0 + r) * CC + c);
            Ps[r][c] = pv.x; Ps[r][c + 1] = pv.y; Ps[r][c + 2] = pv.z; Ps[r][c + 3] = pv.w;
            Vs[r][c] = vv.x; Vs[r][c + 1] = vv.y; Vs[r][c + 2] = vv.z; Vs[r][c + 3] = vv.w;
        }
        __syncthreads();
        #pragma unroll 8
        for (int kk = 0; kk < 64; kk++) {
            float a[4], bb[4];
            #pragma unroll
            for (int i = 0; i < 4; i++) a[i]  = Ps[ty * 4 + i][kk];
            #pragma unroll
            for (int j = 0; j < 4; j++) bb[j] = Vs[kk][tx * 4 + j];
            #pragma unroll
            for (int i = 0; i < 4; i++)
                #pragma unroll
                for (int j = 0; j < 4; j++) acc[i][j] += a[i] * bb[j];
        }
        __syncthreads();
    }
    float* yb = g_y + (size_t)b * TT * CC + h * DH;
    #pragma unroll
    for (int i = 0; i < 4; i++)
        #pragma unroll
        for (int j = 0; j < 4; j++)
            yb[(size_t)(qt + ty * 4 + i) * CC + tx * 4 + j] = acc[i][j];
}

// ---------------- host orchestration ----------------
extern "C" void kernel_launch(void* const* d_in, const int* in_sizes, int n_in,
                              void* d_out, int out_size) {
    const int*   idx  = (const int*)  d_in[0];
    const float* tok  = (const float*)d_in[1];
    const float* pos  = (const float*)d_in[2];
    const float* ln1g = (const float*)d_in[3];
    const float* ln1b = (const float*)d_in[4];
    const float* Wq   = (const float*)d_in[5];
    const float* bq   = (const float*)d_in[6];
    const float* Wk   = (const float*)d_in[7];
    const float* bk   = (const float*)d_in[8];
    const float* Wv   = (const float*)d_in[9];
    const float* bv   = (const float*)d_in[10];
    const float* Wp   = (const float*)d_in[11];
    const float* bp   = (const float*)d_in[12];
    const float* ln2g = (const float*)d_in[13];
    const float* ln2b = (const float*)d_in[14];
    const float* W1   = (const float*)d_in[15];
    const float* b1   = (const float*)d_in[16];
    const float* W2   = (const float*)d_in[17];
    const float* b2   = (const float*)d_in[18];
    const float* lnfg = (const float*)d_in[19];
    const float* lnfb = (const float*)d_in[20];
    const float* Wh   = (const float*)d_in[21];
    float* out = (float*)d_out;

    float *px, *pxn, *pq, *pk, *pv, *py, *ph;
    cudaGetSymbolAddress((void**)&px,  g_x);
    cudaGetSymbolAddress((void**)&pxn, g_xn);
    cudaGetSymbolAddress((void**)&pq,  g_q);
    cudaGetSymbolAddress((void**)&pk,  g_k);
    cudaGetSymbolAddress((void**)&pv,  g_v);
    cudaGetSymbolAddress((void**)&py,  g_y);
    cudaGetSymbolAddress((void**)&ph,  g_h);

    embed_k<<<(MTOK * CC) / 256, 256>>>(idx, tok, pos);

    dim3 gCC(CC / 128, MTOK / 128);     // (4, 32)
    dim3 gCF(CF / 128, MTOK / 128);     // (16, 32)
    dim3 gS(8, 8, BB * HH);             // scores tiles
    dim3 gPV(8, BB * HH);               // pv tiles

    for (int step = 0; step < NSTEPS; step++) {
        for (int l = 0; l < 2; l++) {
            size_t wo  = (size_t)l * CC * CC;
            size_t bo  = (size_t)l * CC;
            size_t w1o = (size_t)l * CC * CF;
            size_t b1o = (size_t)l * CF;

            ln_k<<<MTOK, 256>>>(px, ln1g + bo, ln1b + bo, pxn);
            gemm128_k<false><<<gCC, 256>>>(pxn, Wq + wo, bq + bo, nullptr, pq, MTOK, CC, CC);
            gemm128_k<false><<<gCC, 256>>>(pxn, Wk + wo, bk + bo, nullptr, pk, MTOK, CC, CC);
            gemm128_k<false><<<gCC, 256>>>(pxn, Wv + wo, bv + bo, nullptr, pv, MTOK, CC, CC);
            attn_scores_k<<<gS, 256>>>();
            softmax_k<<<BB * HH * TT, 256>>>();
            attn_pv_k<<<gPV, 256>>>();
            // x = x + y @ Wp + bp
            gemm128_k<false><<<gCC, 256>>>(py, Wp + wo, bp + bo, px, px, MTOK, CC, CC);

            ln_k<<<MTOK, 256>>>(px, ln2g + bo, ln2b + bo, pxn);
            gemm128_k<true ><<<gCF, 256>>>(pxn, W1 + w1o, b1 + b1o, nullptr, ph, MTOK, CF, CC);
            // x = x + h @ W2 + b2
            gemm128_k<false><<<gCC, 256>>>(ph, W2 + w1o, b2 + bo, px, px, MTOK, CC, CF);
        }
    }

    ln_k<<<MTOK, 256>>>(px, lnfg, lnfb, pxn);
    gemm128_k<false><<<dim3(VV / 128, MTOK / 128), 256>>>(pxn, Wh, nullptr, nullptr, out,
                                                          MTOK, VV, CC);
}

// round 3
// speedup vs baseline: 3.2844x; 3.2844x over previous
#include <cuda_runtime.h>
#include <cstdint>
#include <math.h>

#define BB 8
#define TT 512
#define CC 512
#define HH 8
#define DH 64
#define CF 2048
#define MTOK (BB*TT)      // 4096
#define VV 512
#define NSTEPS 4
#define ATT_SCALE 0.125f  // 1/sqrt(64)

// ---------------- scratch (device globals: no allocations allowed) ----------
__device__ float g_x [MTOK*CC];
__device__ float g_xn[MTOK*CC];
__device__ float g_q [MTOK*CC];
__device__ float g_k [MTOK*CC];
__device__ float g_v [MTOK*CC];
__device__ float g_y [MTOK*CC];
__device__ float g_h [MTOK*CF];
__device__ float g_att[(size_t)BB*HH*TT*TT];

// ======================= helpers ==============================
__device__ __forceinline__ uint32_t smem_u32(const void* p) {
    uint32_t a;
    asm("{ .reg .u64 t; cvta.to.shared.u64 t, %1; cvt.u32.u64 %0, t; }"
        : "=r"(a) : "l"(p));
    return a;
}
__device__ __forceinline__ void cp_async16(uint32_t dst, const void* src) {
    asm volatile("cp.async.cg.shared.global [%0], [%1], 16;" :: "r"(dst), "l"(src));
}
__device__ __forceinline__ void cp_commit() {
    asm volatile("cp.async.commit_group;" ::: "memory");
}
template <int N>
__device__ __forceinline__ void cp_wait() {
    asm volatile("cp.async.wait_group %0;" :: "n"(N) : "memory");
}
__device__ __forceinline__ uint32_t f2tf32(float x) {
    uint32_t r;
    asm("cvt.rna.tf32.f32 %0, %1;" : "=r"(r) : "f"(x));
    return r;
}
// D += A @ B  (m16n8k8, tf32 in, fp32 accumulate)
__device__ __forceinline__ void mma8(float* c, const uint32_t* a, const uint32_t* b) {
    asm volatile(
        "mma.sync.aligned.m16n8k8.row.col.f32.tf32.tf32.f32 "
        "{%0,%1,%2,%3}, {%4,%5,%6,%7}, {%8,%9}, {%0,%1,%2,%3};"
        : "+f"(c[0]), "+f"(c[1]), "+f"(c[2]), "+f"(c[3])
        : "r"(a[0]), "r"(a[1]), "r"(a[2]), "r"(a[3]), "r"(b[0]), "r"(b[1]));
}

// ================== dense GEMM: out = epi(A@W + bias + res) ================
// A[M,K] row-major, W[K,N] row-major. CTA tile 128x128, 8 warps (2x4),
// warp tile 64x32, K-chunk 32, cp.async double buffered.
#define AS_STR 36     // banks (4m + k) distinct per quad-group
#define BS_STR 136    // banks (8k + n) distinct per quad-group
#define GEMM_SMEM (2*128*AS_STR*4 + 2*32*BS_STR*4)   // 71680 B

template <bool GELU>
__global__ void __launch_bounds__(256)
mma_gemm_k(const float* __restrict__ A, const float* __restrict__ W,
           const float* __restrict__ bias, const float* __restrict__ res,
           float* __restrict__ out, int M, int N, int K) {
    extern __shared__ char dsm[];
    float* As = (float*)dsm;                       // [2][128][AS_STR]
    float* Bs = As + 2 * 128 * AS_STR;             // [2][32][BS_STR]

    int tid = threadIdx.x;
    int wid = tid >> 5, lane = tid & 31;
    int g = lane >> 2, t = lane & 3;
    int mw = wid >> 2, nw = wid & 3;               // warp grid 2x4
    int m0 = blockIdx.y * 128, n0 = blockIdx.x * 128;

    auto loadA = [&](int chunk, int buf) {
        const float* src = A + (size_t)m0 * K + chunk * 32;
        float* dst = As + buf * 128 * AS_STR;
        #pragma unroll
        for (int i = 0; i < 4; i++) {
            int c = tid + i * 256;                 // 128 rows x 8 segs
            int m = c >> 3, s = c & 7;
            cp_async16(smem_u32(dst + m * AS_STR + s * 4),
                       src + (size_t)m * K + s * 4);
        }
    };
    auto loadB = [&](int chunk, int buf) {
        const float* src = W + (size_t)(chunk * 32) * N + n0;
        float* dst = Bs + buf * 32 * BS_STR;
        #pragma unroll
        for (int i = 0; i < 4; i++) {
            int c = tid + i * 256;                 // 32 rows x 32 segs
            int k = c >> 5, s = c & 31;
            cp_async16(smem_u32(dst + k * BS_STR + s * 4),
                       src + (size_t)k * N + s * 4);
        }
    };

    float acc[4][4][4];
    #pragma unroll
    for (int mi = 0; mi < 4; mi++)
        #pragma unroll
        for (int ni = 0; ni < 4; ni++)
            #pragma unroll
            for (int q = 0; q < 4; q++) acc[mi][ni][q] = 0.0f;

    const int nch = K >> 5;
    loadA(0, 0); loadB(0, 0); cp_commit();

    for (int i = 0; i < nch; i++) {
        int buf = i & 1;
        if (i + 1 < nch) {
            loadA(i + 1, buf ^ 1); loadB(i + 1, buf ^ 1); cp_commit();
            cp_wait<1>();
        } else {
            cp_wait<0>();
        }
        __syncthreads();
        const float* Ab = As + buf * 128 * AS_STR;
        const float* Bb = Bs + buf * 32 * BS_STR;
        #pragma unroll
        for (int ks = 0; ks < 4; ks++) {
            int k0 = ks * 8;
            uint32_t af[4][4], bf[4][2];
            #pragma unroll
            for (int mi = 0; mi < 4; mi++) {
                int row = mw * 64 + mi * 16;
                af[mi][0] = f2tf32(Ab[(row + g)     * AS_STR + k0 + t]);
                af[mi][1] = f2tf32(Ab[(row + 8 + g) * AS_STR + k0 + t]);
                af[mi][2] = f2tf32(Ab[(row + g)     * AS_STR + k0 + t + 4]);
                af[mi][3] = f2tf32(Ab[(row + 8 + g) * AS_STR + k0 + t + 4]);
            }
            #pragma unroll
            for (int ni = 0; ni < 4; ni++) {
                int col = nw * 32 + ni * 8 + g;
                bf[ni][0] = f2tf32(Bb[(k0 + t)     * BS_STR + col]);
                bf[ni][1] = f2tf32(Bb[(k0 + t + 4) * BS_STR + col]);
            }
            #pragma unroll
            for (int mi = 0; mi < 4; mi++)
                #pragma unroll
                for (int ni = 0; ni < 4; ni++)
                    mma8(acc[mi][ni], af[mi], bf[ni]);
        }
        __syncthreads();
    }

    // epilogue
    #pragma unroll
    for (int mi = 0; mi < 4; mi++) {
        #pragma unroll
        for (int ni = 0; ni < 4; ni++) {
            int r0  = m0 + mw * 64 + mi * 16 + g;
            int col = n0 + nw * 32 + ni * 8 + 2 * t;
            #pragma unroll
            for (int h = 0; h < 2; h++) {          // h=0: rows r0, h=1: r0+8
                int r = r0 + 8 * h;
                #pragma unroll
                for (int q = 0; q < 2; q++) {
                    float v = acc[mi][ni][2 * h + q];
                    int c = col + q;
                    if (bias) v += bias[c];
                    if (res)  v += res[(size_t)r * N + c];
                    if (GELU) v = 0.5f * v * (1.0f + erff(v * 0.70710678118654752f));
                    out[(size_t)r * N + c] = v;
                }
            }
        }
    }
}

// ============ attention scores: S = (Q Kt) * scale via mma ================
// per (b,h): Q[512,64] @ K^T[64,512]. CTA tile 128x128, full K=64 resident.
#define QS_STR 68
#define SC_SMEM (2*128*QS_STR*4)                   // 69632 B

__global__ void __launch_bounds__(256)
attn_scores_k() {
    extern __shared__ char dsm[];
    float* Qs = (float*)dsm;                       // [128][QS_STR]
    float* Ks = Qs + 128 * QS_STR;                 // [128][QS_STR]

    int tid = threadIdx.x;
    int wid = tid >> 5, lane = tid & 31;
    int g = lane >> 2, t = lane & 3;
    int mw = wid >> 2, nw = wid & 3;
    int z = blockIdx.z;                            // b*H + h
    int b = z >> 3, h = z & 7;
    int qt = blockIdx.y * 128, kt = blockIdx.x * 128;

    const float* qb = g_q + ((size_t)b * TT) * CC + h * DH;
    const float* kb = g_k + ((size_t)b * TT) * CC + h * DH;
    #pragma unroll
    for (int i = 0; i < 8; i++) {
        int c = tid + i * 256;                     // 128 rows x 16 segs
        int r = c >> 4, s = c & 15;
        cp_async16(smem_u32(Qs + r * QS_STR + s * 4),
                   qb + (size_t)(qt + r) * CC + s * 4);
        cp_async16(smem_u32(Ks + r * QS_STR + s * 4),
                   kb + (size_t)(kt + r) * CC + s * 4);
    }
    cp_commit(); cp_wait<0>();
    __syncthreads();

    float acc[4][4][4] = {};
    #pragma unroll
    for (int ks = 0; ks < 8; ks++) {
        int k0 = ks * 8;
        uint32_t af[4][4], bf[4][2];
        #pragma unroll
        for (int mi = 0; mi < 4; mi++) {
            int row = mw * 64 + mi * 16;
            af[mi][0] = f2tf32(Qs[(row + g)     * QS_STR + k0 + t]);
            af[mi][1] = f2tf32(Qs[(row + 8 + g) * QS_STR + k0 + t]);
            af[mi][2] = f2tf32(Qs[(row + g)     * QS_STR + k0 + t + 4]);
            af[mi][3] = f2tf32(Qs[(row + 8 + g) * QS_STR + k0 + t + 4]);
        }
        #pragma unroll
        for (int ni = 0; ni < 4; ni++) {
            int col = nw * 32 + ni * 8 + g;        // K row = score column
            bf[ni][0] = f2tf32(Ks[col * QS_STR + k0 + t]);
            bf[ni][1] = f2tf32(Ks[col * QS_STR + k0 + t + 4]);
        }
        #pragma unroll
        for (int mi = 0; mi < 4; mi++)
            #pragma unroll
            for (int ni = 0; ni < 4; ni++)
                mma8(acc[mi][ni], af[mi], bf[ni]);
    }

    float* op = g_att + (size_t)z * TT * TT;
    #pragma unroll
    for (int mi = 0; mi < 4; mi++)
        #pragma unroll
        for (int ni = 0; ni < 4; ni++) {
            int r0  = qt + mw * 64 + mi * 16 + g;
            int col = kt + nw * 32 + ni * 8 + 2 * t;
            op[(size_t)r0       * TT + col]     = acc[mi][ni][0] * ATT_SCALE;
            op[(size_t)r0       * TT + col + 1] = acc[mi][ni][1] * ATT_SCALE;
            op[(size_t)(r0 + 8) * TT + col]     = acc[mi][ni][2] * ATT_SCALE;
            op[(size_t)(r0 + 8) * TT + col + 1] = acc[mi][ni][3] * ATT_SCALE;
        }
}

// ============ Y = P @ V via mma: per (b,h) [512,512]@[512,64] ==============
#define PS_STR 68
#define VS_STR 72
#define PV_SMEM (128*PS_STR*4 + 64*VS_STR*4)       // 53248 B

__global__ void __launch_bounds__(256)
attn_pv_k() {
    extern __shared__ char dsm[];
    float* Ps = (float*)dsm;                       // [128][PS_STR]
    float* Vs = Ps + 128 * PS_STR;                 // [64][VS_STR]

    int tid = threadIdx.x;
    int wid = tid >> 5, lane = tid & 31;
    int g = lane >> 2, t = lane & 3;
    int mw = wid & 3, nw = wid >> 2;               // warp grid 4(m) x 2(n), tile 32x32
    int z = blockIdx.y;
    int b = z >> 3, h = z & 7;
    int qt = blockIdx.x * 128;

    const float* pb = g_att + (size_t)z * TT * TT;
    const float* vb = g_v + ((size_t)b * TT) * CC + h * DH;

    float acc[2][4][4] = {};

    for (int kc = 0; kc < 8; kc++) {               // K chunks of 64
        int kk0 = kc * 64;
        __syncthreads();
        #pragma unroll
        for (int i = 0; i < 8; i++) {              // P: 128 rows x 16 segs
            int c = tid + i * 256;
            int r = c >> 4, s = c & 15;
            cp_async16(smem_u32(Ps + r * PS_STR + s * 4),
                       pb + (size_t)(qt + r) * TT + kk0 + s * 4);
        }
        #pragma unroll
        for (int i = 0; i < 4; i++) {              // V: 64 rows x 16 segs
            int c = tid + i * 256;
            int r = c >> 4, s = c & 15;
            cp_async16(smem_u32(Vs + r * VS_STR + s * 4),
                       vb + (size_t)(kk0 + r) * CC + s * 4);
        }
        cp_commit(); cp_wait<0>();
        __syncthreads();

        #pragma unroll
        for (int ks = 0; ks < 8; ks++) {
            int k0 = ks * 8;
            uint32_t af[2][4], bf[4][2];
            #pragma unroll
            for (int mi = 0; mi < 2; mi++) {
                int row = mw * 32 + mi * 16;
                af[mi][0] = f2tf32(Ps[(row + g)     * PS_STR + k0 + t]);
                af[mi][1] = f2tf32(Ps[(row + 8 + g) * PS_STR + k0 + t]);
                af[mi][2] = f2tf32(Ps[(row + g)     * PS_STR + k0 + t + 4]);
                af[mi][3] = f2tf32(Ps[(row + 8 + g) * PS_STR + k0 + t + 4]);
            }
            #pragma unroll
            for (int ni = 0; ni < 4; ni++) {
                int col = nw * 32 + ni * 8 + g;
                bf[ni][0] = f2tf32(Vs[(k0 + t)     * VS_STR + col]);
                bf[ni][1] = f2tf32(Vs[(k0 + t + 4) * VS_STR + col]);
            }
            #pragma unroll
            for (int mi = 0; mi < 2; mi++)
                #pragma unroll
                for (int ni = 0; ni < 4; ni++)
                    mma8(acc[mi][ni], af[mi], bf[ni]);
        }
    }

    float* yb = g_y + ((size_t)b * TT) * CC + h * DH;
    #pragma unroll
    for (int mi = 0; mi < 2; mi++)
        #pragma unroll
        for (int ni = 0; ni < 4; ni++) {
            int r0  = qt + mw * 32 + mi * 16 + g;
            int col = nw * 32 + ni * 8 + 2 * t;
            yb[(size_t)r0       * CC + col]     = acc[mi][ni][0];
            yb[(size_t)r0       * CC + col + 1] = acc[mi][ni][1];
            yb[(size_t)(r0 + 8) * CC + col]     = acc[mi][ni][2];
            yb[(size_t)(r0 + 8) * CC + col + 1] = acc[mi][ni][3];
        }
}

// ---------------- block reductions ----------------
__device__ __forceinline__ float block_reduce_sum(float v, float* sm) {
    #pragma unroll
    for (int o = 16; o; o >>= 1) v += __shfl_xor_sync(0xffffffffu, v, o);
    int w = threadIdx.x >> 5;
    if ((threadIdx.x & 31) == 0) sm[w] = v;
    __syncthreads();
    if (threadIdx.x < 32) {
        float x = (threadIdx.x < 8) ? sm[threadIdx.x] : 0.0f;
        #pragma unroll
        for (int o = 4; o; o >>= 1) x += __shfl_xor_sync(0xffffffffu, x, o);
        if (threadIdx.x == 0) sm[0] = x;
    }
    __syncthreads();
    float r = sm[0];
    __syncthreads();
    return r;
}
__device__ __forceinline__ float block_reduce_max(float v, float* sm) {
    #pragma unroll
    for (int o = 16; o; o >>= 1) v = fmaxf(v, __shfl_xor_sync(0xffffffffu, v, o));
    int w = threadIdx.x >> 5;
    if ((threadIdx.x & 31) == 0) sm[w] = v;
    __syncthreads();
    if (threadIdx.x < 32) {
        float x = (threadIdx.x < 8) ? sm[threadIdx.x] : -1e30f;
        #pragma unroll
        for (int o = 4; o; o >>= 1) x = fmaxf(x, __shfl_xor_sync(0xffffffffu, x, o));
        if (threadIdx.x == 0) sm[0] = x;
    }
    __syncthreads();
    float r = sm[0];
    __syncthreads();
    return r;
}

// ---------------- embedding ----------------
__global__ void embed_k(const int* __restrict__ idx, const float* __restrict__ tok,
                        const float* __restrict__ pos) {
    int i = blockIdx.x * blockDim.x + threadIdx.x;
    int m = i / CC, c = i - m * CC;
    int t = m & (TT - 1);
    g_x[i] = tok[idx[m] * CC + c] + pos[t * CC + c];
}

// ---------------- layernorm ----------------
__global__ void ln_k(const float* __restrict__ in, const float* __restrict__ gam,
                     const float* __restrict__ bet, float* __restrict__ out) {
    __shared__ float sm[8];
    int row = blockIdx.x;
    const float* x = in + (size_t)row * CC;
    int t = threadIdx.x;
    float v0 = x[t], v1 = x[t + 256];
    float mean = block_reduce_sum(v0 + v1, sm) * (1.0f / CC);
    float d0 = v0 - mean, d1 = v1 - mean;
    float var = block_reduce_sum(d0 * d0 + d1 * d1, sm) * (1.0f / CC);
    float rstd = rsqrtf(var + 1e-5f);
    float* o = out + (size_t)row * CC;
    o[t]       = d0 * rstd * gam[t]       + bet[t];
    o[t + 256] = d1 * rstd * gam[t + 256] + bet[t + 256];
}

// ---------------- softmax ----------------
__global__ void softmax_k() {
    __shared__ float sm[8];
    size_t row = blockIdx.x;
    float* p = g_att + row * TT;
    int t = threadIdx.x;
    float v0 = p[t], v1 = p[t + 256];
    float mx = block_reduce_max(fmaxf(v0, v1), sm);
    float e0 = expf(v0 - mx), e1 = expf(v1 - mx);
    float s = block_reduce_sum(e0 + e1, sm);
    float inv = 1.0f / s;
    p[t] = e0 * inv;
    p[t + 256] = e1 * inv;
}

// ---------------- host orchestration ----------------
extern "C" void kernel_launch(void* const* d_in, const int* in_sizes, int n_in,
                              void* d_out, int out_size) {
    const int*   idx  = (const int*)  d_in[0];
    const float* tok  = (const float*)d_in[1];
    const float* pos  = (const float*)d_in[2];
    const float* ln1g = (const float*)d_in[3];
    const float* ln1b = (const float*)d_in[4];
    const float* Wq   = (const float*)d_in[5];
    const float* bq   = (const float*)d_in[6];
    const float* Wk   = (const float*)d_in[7];
    const float* bk   = (const float*)d_in[8];
    const float* Wv   = (const float*)d_in[9];
    const float* bv   = (const float*)d_in[10];
    const float* Wp   = (const float*)d_in[11];
    const float* bp   = (const float*)d_in[12];
    const float* ln2g = (const float*)d_in[13];
    const float* ln2b = (const float*)d_in[14];
    const float* W1   = (const float*)d_in[15];
    const float* b1   = (const float*)d_in[16];
    const float* W2   = (const float*)d_in[17];
    const float* b2   = (const float*)d_in[18];
    const float* lnfg = (const float*)d_in[19];
    const float* lnfb = (const float*)d_in[20];
    const float* Wh   = (const float*)d_in[21];
    float* out = (float*)d_out;

    float *px, *pxn, *pq, *pk, *pv, *py, *ph;
    cudaGetSymbolAddress((void**)&px,  g_x);
    cudaGetSymbolAddress((void**)&pxn, g_xn);
    cudaGetSymbolAddress((void**)&pq,  g_q);
    cudaGetSymbolAddress((void**)&pk,  g_k);
    cudaGetSymbolAddress((void**)&pv,  g_v);
    cudaGetSymbolAddress((void**)&py,  g_y);
    cudaGetSymbolAddress((void**)&ph,  g_h);

    cudaFuncSetAttribute(mma_gemm_k<false>,
                         cudaFuncAttributeMaxDynamicSharedMemorySize, GEMM_SMEM);
    cudaFuncSetAttribute(mma_gemm_k<true>,
                         cudaFuncAttributeMaxDynamicSharedMemorySize, GEMM_SMEM);
    cudaFuncSetAttribute(attn_scores_k,
                         cudaFuncAttributeMaxDynamicSharedMemorySize, SC_SMEM);
    cudaFuncSetAttribute(attn_pv_k,
                         cudaFuncAttributeMaxDynamicSharedMemorySize, PV_SMEM);

    embed_k<<<(MTOK * CC) / 256, 256>>>(idx, tok, pos);

    dim3 gCC(CC / 128, MTOK / 128);     // (4, 32)
    dim3 gCF(CF / 128, MTOK / 128);     // (16, 32)
    dim3 gS(4, 4, BB * HH);             // scores: 128x128 tiles
    dim3 gPV(4, BB * HH);               // pv: 128-row tiles

    for (int step = 0; step < NSTEPS; step++) {
        for (int l = 0; l < 2; l++) {
            size_t wo  = (size_t)l * CC * CC;
            size_t bo  = (size_t)l * CC;
            size_t w1o = (size_t)l * CC * CF;
            size_t b1o = (size_t)l * CF;

            ln_k<<<MTOK, 256>>>(px, ln1g + bo, ln1b + bo, pxn);
            mma_gemm_k<false><<<gCC, 256, GEMM_SMEM>>>(pxn, Wq + wo, bq + bo, nullptr, pq, MTOK, CC, CC);
            mma_gemm_k<false><<<gCC, 256, GEMM_SMEM>>>(pxn, Wk + wo, bk + bo, nullptr, pk, MTOK, CC, CC);
            mma_gemm_k<false><<<gCC, 256, GEMM_SMEM>>>(pxn, Wv + wo, bv + bo, nullptr, pv, MTOK, CC, CC);
            attn_scores_k<<<gS, 256, SC_SMEM>>>();
            softmax_k<<<BB * HH * TT, 256>>>();
            attn_pv_k<<<gPV, 256, PV_SMEM>>>();
            // x = x + y @ Wp + bp
            mma_gemm_k<false><<<gCC, 256, GEMM_SMEM>>>(py, Wp + wo, bp + bo, px, px, MTOK, CC, CC);

            ln_k<<<MTOK, 256>>>(px, ln2g + bo, ln2b + bo, pxn);
            mma_gemm_k<true ><<<gCF, 256, GEMM_SMEM>>>(pxn, W1 + w1o, b1 + b1o, nullptr, ph, MTOK, CF, CC);
            // x = x + h @ W2 + b2
            mma_gemm_k<false><<<gCC, 256, GEMM_SMEM>>>(ph, W2 + w1o, b2 + bo, px, px, MTOK, CC, CF);
        }
    }

    ln_k<<<MTOK, 256>>>(px, lnfg, lnfb, pxn);
    mma_gemm_k<false><<<dim3(VV / 128, MTOK / 128), 256, GEMM_SMEM>>>(pxn, Wh, nullptr, nullptr, out,
                                                                      MTOK, VV, CC);
}